// round 15
// baseline (speedup 1.0000x reference)
#include <cuda_runtime.h>
#include <cuda_fp16.h>
#include <math.h>

// fp16 coefficient cells, AB/CD interleaved at line granularity.
// Block = 4x2 cells (cx block of 4, cy block of 2). Per block: 256B =
//   line 0 (128B): AB data for the 8 cells   (batches 0,1)
//   line 1 (128B): CD data for the 8 cells   (batches 2,3)
// Cell data (uint4 = 4 half2):
//   .x = (p00a, p00b)            c0
//   .y = (p10-p00 diffs)         cx   (x first difference, top row)
//   .z = (p01a, p01b)            c01
//   .w = (p11-p01 diffs)         cx2  (x first difference, bottom row)
// bilerp = fma(wy, bot-top, top), top = fma(wx, cx, c0), bot = fma(wx, cx2, c01)
// Cell (cy,cx) = image cell (y0=cy-4, x0=cx-4); m = circle-masked image.
// g_pk: normal orientation; g_pkT: transposed image.
#define PACK_DIM 264
#define PACK_SZ (PACK_DIM * PACK_DIM)
#define PK_U4 (PACK_SZ * 2)          // 2 uint4 slots per cell (AB + CD)
#define OUT_N (4 * 180 * 256)
__device__ uint4 g_pk [PK_U4];
__device__ uint4 g_pkT[PK_U4];

// uint4 index of the AB slot for cell (cy,cx); CD slot = +8.
__device__ __forceinline__ int swiz(int cy, int cx) {
    // block = (cy>>1)*66 + (cx>>2); 16 uint4 per block
    return ((cy >> 1) * 66 + (cx >> 2)) * 16 + ((cy & 1) << 2) + (cx & 3);
}

__device__ __forceinline__ unsigned h2(float a, float b) {
    __half2 h = __floats2half2_rn(a, b);
    return *reinterpret_cast<unsigned*>(&h);
}

__device__ __forceinline__ __half2 u2h(unsigned u) {
    return *reinterpret_cast<__half2*>(&u);
}

__global__ __launch_bounds__(256) void pack_kernel(const float* __restrict__ x,
                                                   float* __restrict__ out) {
    int idx = blockIdx.x * blockDim.x + threadIdx.x;
    // zero the output (radon kernel accumulates via atomics)
    for (int o = idx; o < OUT_N; o += gridDim.x * blockDim.x)
        out[o] = 0.0f;
    if (idx >= PACK_SZ) return;
    int cy = idx / PACK_DIM;
    int cx = idx - cy * PACK_DIM;
    // cells with center radius > 134 are never read (sample radius <= 131)
    {
        int ddx = cx - 131, ddy = cy - 131;
        if (ddx * ddx + ddy * ddy > 134 * 134) return;
    }
    int y0 = cy - 4;
    int x0 = cx - 4;

    auto get = [&](int b, int yi, int xi) -> float {
        if ((unsigned)yi > 255u || (unsigned)xi > 255u) return 0.0f;
        int dx = xi - 128, dy = yi - 128;
        if (dx * dx + dy * dy > 16384) return 0.0f;
        return x[b * 65536 + yi * 256 + xi];
    };

    float a00 = get(0, y0, x0),     b00 = get(1, y0, x0);
    float a10 = get(0, y0, x0 + 1), b10 = get(1, y0, x0 + 1);
    float a01 = get(0, y0 + 1, x0), b01 = get(1, y0 + 1, x0);
    float a11 = get(0, y0 + 1, x0 + 1), b11 = get(1, y0 + 1, x0 + 1);
    float c00 = get(2, y0, x0),     d00 = get(3, y0, x0);
    float c10 = get(2, y0, x0 + 1), d10 = get(3, y0, x0 + 1);
    float c01 = get(2, y0 + 1, x0), d01 = get(3, y0 + 1, x0);
    float c11 = get(2, y0 + 1, x0 + 1), d11 = get(3, y0 + 1, x0 + 1);

    int sn = swiz(cy, cx);
    g_pk[sn]     = make_uint4(h2(a00, b00), h2(a10 - a00, b10 - b00),
                              h2(a01, b01), h2(a11 - a01, b11 - b01));
    g_pk[sn + 8] = make_uint4(h2(c00, d00), h2(c10 - c00, d10 - d00),
                              h2(c01, d01), h2(c11 - c01, d11 - d01));

    // Transposed-image cell at (cx, cy): T00=n00, T10=n01, T01=n10, T11=n11.
    int st = swiz(cx, cy);
    g_pkT[st]     = make_uint4(h2(a00, b00), h2(a01 - a00, b01 - b00),
                               h2(a10, b10), h2(a11 - a10, b11 - b10));
    g_pkT[st + 8] = make_uint4(h2(c00, d00), h2(c01 - c00, d01 - d00),
                               h2(c10, d10), h2(c11 - c10, d11 - d10));
}

// Warp = 4 adjacent rays x 8 consecutive samples (compact ~8x4-cell patch per
// LDG). 4 i-segments (blockIdx.z); segments combine via atomicAdd.
// Unroll x3 (MLP = 6). __launch_bounds__(256, 8) pins regs at 32 -> 8 CTA/SM.
__global__ __launch_bounds__(256, 8) void radon_kernel(float* __restrict__ out) {
    const int a = blockIdx.y;                  // angle 0..179
    const int warp = threadIdx.x >> 5;
    const int lane = threadIdx.x & 31;
    const int r = lane >> 3;                   // ray-in-warp 0..3
    const int k = lane & 7;                    // sample phase 0..7
    const int j = blockIdx.x * 32 + warp * 4 + r;
    const int z = blockIdx.z;                  // segment 0..3

    float ang = (float)a * (float)(M_PI / 179.0);
    float s, c;
    sincosf(ang, &s, &c);

    const float v = (float)j - 127.5f;

    // R=131 > 130.13 = max radius of any reference-contributing sample.
    const float RR = 131.0f * 131.0f;
    float umax = sqrtf(fmaxf(RR - v * v, 0.0f));
    int ilo = max(0,   (int)ceilf (127.5f - umax));
    int ihi = min(255, (int)floorf(127.5f + umax));
    int len = ihi - ilo + 1;

    // contiguous quarter-segment for this z
    int i0 = ilo + ((len * z) >> 2);
    int i1 = ilo + ((len * (z + 1)) >> 2) - 1;

    // Orientation: walk slope |se/ce| <= 1 (bilerp(img,px,py)==bilerp(imgT,py,px)).
    // 131.5 = 127.5 + 4 cell padding, so floor(px) is the padded cell index.
    const bool swp = fabsf(s) > fabsf(c);
    float ce, se, px0, py0;
    if (!swp) {
        ce = c; se = s;
        px0 = fmaf(-127.5f, c, fmaf(-s, v, 131.5f));
        py0 = fmaf(-127.5f, s, fmaf( c, v, 131.5f));
    } else {
        ce = s; se = c;
        px0 = fmaf(-127.5f, s, fmaf( c, v, 131.5f));
        py0 = fmaf(-127.5f, c, fmaf(-s, v, 131.5f));
    }
    const uint4* __restrict__ PK = swp ? g_pkT : g_pk;

    float acc0 = 0.f, acc1 = 0.f, acc2 = 0.f, acc3 = 0.f;

    auto sample = [&](float fi) {
        float px = fmaf(fi, ce, px0);
        float py = fmaf(fi, se, py0);
        float fx = floorf(px), fy = floorf(py);
        int idx = swiz((int)fy, (int)fx);
        uint4 ab = __ldg(&PK[idx]);
        uint4 cd = __ldg(&PK[idx + 8]);     // same block, next 128B line
        __half2 wx2 = __float2half2_rn(px - fx);
        __half2 wy2 = __float2half2_rn(py - fy);
        __half2 tA = __hfma2(wx2, u2h(ab.y), u2h(ab.x));
        __half2 bA = __hfma2(wx2, u2h(ab.w), u2h(ab.z));
        __half2 rA = __hfma2(wy2, __hsub2(bA, tA), tA);
        float2 fA = __half22float2(rA);
        __half2 tC = __hfma2(wx2, u2h(cd.y), u2h(cd.x));
        __half2 bC = __hfma2(wx2, u2h(cd.w), u2h(cd.z));
        __half2 rC = __hfma2(wy2, __hsub2(bC, tC), tC);
        float2 fC = __half22float2(rC);
        acc0 += fA.x;
        acc1 += fA.y;
        acc2 += fC.x;
        acc3 += fC.y;
    };

    float fi = (float)(i0 + k);
    int n = i1 - (i0 + k);          // sample fi valid iff n >= 0

    // unroll x3: samples fi, fi+8, fi+16 per trip (MLP = 6 loads in flight)
    for (; n >= 16; n -= 24, fi += 24.0f) {
        sample(fi);
        sample(fi + 8.0f);
        sample(fi + 16.0f);
    }
    if (n >= 8) {
        sample(fi);
        sample(fi + 8.0f);
    } else if (n >= 0) {
        sample(fi);
    }

    // segmented reduction over the 8-lane octet
    #pragma unroll
    for (int o = 4; o > 0; o >>= 1) {
        acc0 += __shfl_down_sync(0xFFFFFFFFu, acc0, o, 8);
        acc1 += __shfl_down_sync(0xFFFFFFFFu, acc1, o, 8);
        acc2 += __shfl_down_sync(0xFFFFFFFFu, acc2, o, 8);
        acc3 += __shfl_down_sync(0xFFFFFFFFu, acc3, o, 8);
    }

    if (k == 0) {
        int o = a * 256 + j;
        atomicAdd(&out[o],          acc0);
        atomicAdd(&out[o +  46080], acc1);
        atomicAdd(&out[o +  92160], acc2);
        atomicAdd(&out[o + 138240], acc3);
    }
}

extern "C" void kernel_launch(void* const* d_in, const int* in_sizes, int n_in,
                              void* d_out, int out_size) {
    const float* x = (const float*)d_in[0];
    float* out = (float*)d_out;

    pack_kernel<<<(PACK_SZ + 255) / 256, 256>>>(x, out);

    dim3 grid(8, 180, 4);   // 8 j-groups x 180 angles x 4 i-segments
    radon_kernel<<<grid, 256>>>(out);
}

// round 16
// speedup vs baseline: 1.0423x; 1.0423x over previous
#include <cuda_runtime.h>
#include <cuda_fp16.h>
#include <math.h>

// fp16 coefficient-cell arrays with 4x2 cell blocking (one 128B line = 8 cells,
// 4 wide x 2 tall). Cell (cy,cx) = image cell (y0=cy-4, x0=cx-4):
//   .x = (pA00, pB00)            c0
//   .y = (pA10-pA00, pB10-pB00)  cx   (x first difference, top row)
//   .z = (pA01, pB01)            c01
//   .w = (pA11-pA01, pB11-pB01)  cx2  (x first difference, bottom row)
// bilerp = fma(wy, bot-top, top), top = fma(wx, cx, c0), bot = fma(wx, cx2, c01)
// m = circle-masked image (R=128, center 128), 0 outside [0,256)^2.
// g_ab: batches 0,1   g_cd: batches 2,3   *_T: transposed image.
#define PACK_DIM 264
#define PACK_SZ (PACK_DIM * PACK_DIM)
#define OUT_N (4 * 180 * 256)
__device__ uint4 g_ab [PACK_SZ];
__device__ uint4 g_cd [PACK_SZ];
__device__ uint4 g_abT[PACK_SZ];
__device__ uint4 g_cdT[PACK_SZ];

__device__ __forceinline__ int swiz(int cy, int cx) {
    return (cy >> 1) * 528 + (cx >> 2) * 8 + ((cy & 1) << 2) + (cx & 3);
}

__device__ __forceinline__ unsigned h2(float a, float b) {
    __half2 h = __floats2half2_rn(a, b);
    return *reinterpret_cast<unsigned*>(&h);
}

__device__ __forceinline__ __half2 u2h(unsigned u) {
    return *reinterpret_cast<__half2*>(&u);
}

__global__ __launch_bounds__(256) void pack_kernel(const float* __restrict__ x,
                                                   float* __restrict__ out) {
    int idx = blockIdx.x * blockDim.x + threadIdx.x;
    // zero the output (radon kernel accumulates via atomics)
    for (int o = idx; o < OUT_N; o += gridDim.x * blockDim.x)
        out[o] = 0.0f;
    if (idx >= PACK_SZ) return;
    int cy = idx / PACK_DIM;
    int cx = idx - cy * PACK_DIM;
    // cells with center radius > 134 are never read (sample radius <= 131)
    {
        int ddx = cx - 131, ddy = cy - 131;
        if (ddx * ddx + ddy * ddy > 134 * 134) return;
    }
    int y0 = cy - 4;
    int x0 = cx - 4;

    auto get = [&](int b, int yi, int xi) -> float {
        if ((unsigned)yi > 255u || (unsigned)xi > 255u) return 0.0f;
        int dx = xi - 128, dy = yi - 128;
        if (dx * dx + dy * dy > 16384) return 0.0f;
        return x[b * 65536 + yi * 256 + xi];
    };

    float a00 = get(0, y0, x0),     b00 = get(1, y0, x0);
    float a10 = get(0, y0, x0 + 1), b10 = get(1, y0, x0 + 1);
    float a01 = get(0, y0 + 1, x0), b01 = get(1, y0 + 1, x0);
    float a11 = get(0, y0 + 1, x0 + 1), b11 = get(1, y0 + 1, x0 + 1);
    float c00 = get(2, y0, x0),     d00 = get(3, y0, x0);
    float c10 = get(2, y0, x0 + 1), d10 = get(3, y0, x0 + 1);
    float c01 = get(2, y0 + 1, x0), d01 = get(3, y0 + 1, x0);
    float c11 = get(2, y0 + 1, x0 + 1), d11 = get(3, y0 + 1, x0 + 1);

    int sn = swiz(cy, cx);
    g_ab[sn] = make_uint4(h2(a00, b00), h2(a10 - a00, b10 - b00),
                          h2(a01, b01), h2(a11 - a01, b11 - b01));
    g_cd[sn] = make_uint4(h2(c00, d00), h2(c10 - c00, d10 - d00),
                          h2(c01, d01), h2(c11 - c01, d11 - d01));

    // Transposed-image cell at (cx, cy): T00=n00, T10=n01, T01=n10, T11=n11.
    int st = swiz(cx, cy);
    g_abT[st] = make_uint4(h2(a00, b00), h2(a01 - a00, b01 - b00),
                           h2(a10, b10), h2(a11 - a10, b11 - b10));
    g_cdT[st] = make_uint4(h2(c00, d00), h2(c01 - c00, d01 - d00),
                           h2(c10, d10), h2(c11 - c10, d11 - d10));
}

// Warp = 4 adjacent rays x 8 consecutive samples (compact ~8x4-cell patch per
// LDG, 4x2-blocked lines). 4 i-segments (blockIdx.z); atomicAdd combine.
// Unroll x3 (MLP = 6). CTA = 128 threads: 34 regs -> 15 CTAs/SM = 60 warps
// (93.75% cap) and small retire quanta for better load balance.
__global__ __launch_bounds__(128) void radon_kernel(float* __restrict__ out) {
    const int a = blockIdx.y;                  // angle 0..179
    const int warp = threadIdx.x >> 5;         // 0..3
    const int lane = threadIdx.x & 31;
    const int r = lane >> 3;                   // ray-in-warp 0..3
    const int k = lane & 7;                    // sample phase 0..7
    const int j = blockIdx.x * 16 + warp * 4 + r;
    const int z = blockIdx.z;                  // segment 0..3

    float ang = (float)a * (float)(M_PI / 179.0);
    float s, c;
    sincosf(ang, &s, &c);

    const float v = (float)j - 127.5f;

    // R=131 > 130.13 = max radius of any reference-contributing sample.
    const float RR = 131.0f * 131.0f;
    float umax = sqrtf(fmaxf(RR - v * v, 0.0f));
    int ilo = max(0,   (int)ceilf (127.5f - umax));
    int ihi = min(255, (int)floorf(127.5f + umax));
    int len = ihi - ilo + 1;

    // contiguous quarter-segment for this z
    int i0 = ilo + ((len * z) >> 2);
    int i1 = ilo + ((len * (z + 1)) >> 2) - 1;

    // Orientation: walk slope |se/ce| <= 1 (bilerp(img,px,py)==bilerp(imgT,py,px)).
    // 131.5 = 127.5 + 4 cell padding, so floor(px) is the padded cell index.
    const bool swp = fabsf(s) > fabsf(c);
    float ce, se, px0, py0;
    if (!swp) {
        ce = c; se = s;
        px0 = fmaf(-127.5f, c, fmaf(-s, v, 131.5f));
        py0 = fmaf(-127.5f, s, fmaf( c, v, 131.5f));
    } else {
        ce = s; se = c;
        px0 = fmaf(-127.5f, s, fmaf( c, v, 131.5f));
        py0 = fmaf(-127.5f, c, fmaf(-s, v, 131.5f));
    }
    const uint4* __restrict__ AB = swp ? g_abT : g_ab;
    const uint4* __restrict__ CD = swp ? g_cdT : g_cd;

    float acc0 = 0.f, acc1 = 0.f, acc2 = 0.f, acc3 = 0.f;

    auto sample = [&](float fi) {
        float px = fmaf(fi, ce, px0);
        float py = fmaf(fi, se, py0);
        float fx = floorf(px), fy = floorf(py);
        int idx = swiz((int)fy, (int)fx);
        uint4 ab = __ldg(&AB[idx]);
        uint4 cd = __ldg(&CD[idx]);
        __half2 wx2 = __float2half2_rn(px - fx);
        __half2 wy2 = __float2half2_rn(py - fy);
        __half2 tA = __hfma2(wx2, u2h(ab.y), u2h(ab.x));
        __half2 bA = __hfma2(wx2, u2h(ab.w), u2h(ab.z));
        __half2 rA = __hfma2(wy2, __hsub2(bA, tA), tA);
        float2 fA = __half22float2(rA);
        __half2 tC = __hfma2(wx2, u2h(cd.y), u2h(cd.x));
        __half2 bC = __hfma2(wx2, u2h(cd.w), u2h(cd.z));
        __half2 rC = __hfma2(wy2, __hsub2(bC, tC), tC);
        float2 fC = __half22float2(rC);
        acc0 += fA.x;
        acc1 += fA.y;
        acc2 += fC.x;
        acc3 += fC.y;
    };

    float fi = (float)(i0 + k);
    int n = i1 - (i0 + k);          // sample fi valid iff n >= 0

    // unroll x3: samples fi, fi+8, fi+16 per trip (MLP = 6 loads in flight)
    for (; n >= 16; n -= 24, fi += 24.0f) {
        sample(fi);
        sample(fi + 8.0f);
        sample(fi + 16.0f);
    }
    if (n >= 8) {
        sample(fi);
        sample(fi + 8.0f);
    } else if (n >= 0) {
        sample(fi);
    }

    // segmented reduction over the 8-lane octet
    #pragma unroll
    for (int o = 4; o > 0; o >>= 1) {
        acc0 += __shfl_down_sync(0xFFFFFFFFu, acc0, o, 8);
        acc1 += __shfl_down_sync(0xFFFFFFFFu, acc1, o, 8);
        acc2 += __shfl_down_sync(0xFFFFFFFFu, acc2, o, 8);
        acc3 += __shfl_down_sync(0xFFFFFFFFu, acc3, o, 8);
    }

    if (k == 0) {
        int o = a * 256 + j;
        atomicAdd(&out[o],          acc0);
        atomicAdd(&out[o +  46080], acc1);
        atomicAdd(&out[o +  92160], acc2);
        atomicAdd(&out[o + 138240], acc3);
    }
}

extern "C" void kernel_launch(void* const* d_in, const int* in_sizes, int n_in,
                              void* d_out, int out_size) {
    const float* x = (const float*)d_in[0];
    float* out = (float*)d_out;

    pack_kernel<<<(PACK_SZ + 255) / 256, 256>>>(x, out);

    dim3 grid(16, 180, 4);   // 16 j-groups x 180 angles x 4 i-segments
    radon_kernel<<<grid, 128>>>(out);
}